// round 1
// baseline (speedup 1.0000x reference)
#include <cuda_runtime.h>
#include <math.h>

#define B_  8
#define T_  4096
#define C_  64
#define F_  256
#define NL  8          // residual layers (dilations 2..256)
#define M_  (B_ * T_)  // 32768 rows

// Activation state buffers (static device globals — no runtime allocation).
__device__ float g_out [M_ * F_];  // residual stream [B*T, 256]
__device__ float g_skip[M_ * F_];  // skip accumulator
__device__ float g_z   [M_ * F_];  // gated activation per layer

__device__ __forceinline__ float sigmoidf_(float x) {
    return 1.0f / (1.0f + expf(-x));
}
__device__ __forceinline__ float seluf_(float x) {
    const float sc = 1.0507009873554804934193349852946f;
    const float al = 1.6732632423543772848170429916717f;
    return x > 0.0f ? sc * x : sc * al * (expf(x) - 1.0f);
}

// ---------------------------------------------------------------------------
// conv0: out[m,n] = x[b,t-1,:]·Wc[0,:,n] + x[b,t,:]·Wc[1,:,n]
// A[m,k]: k<64 -> x[b,t-1,k] (0 if t==0), else x[b,t,k-64].  B = Wc flat [128,256].
// Tile: BM=64, BN=64, Kb=16. 256 threads, 4x4 per thread.
// ---------------------------------------------------------------------------
__global__ void conv0_kernel(const float* __restrict__ x,
                             const float* __restrict__ Wc) {
    __shared__ float As[16][64];
    __shared__ float Bs[16][64];
    const int tid = threadIdx.x;
    const int tx = tid & 15, ty = tid >> 4;
    const int m0 = blockIdx.x * 64;
    const int n0 = blockIdx.y * 64;
    const int b  = m0 / T_;
    const int t0 = m0 % T_;

    float acc[4][4];
    #pragma unroll
    for (int i = 0; i < 4; ++i)
        #pragma unroll
        for (int j = 0; j < 4; ++j) acc[i][j] = 0.0f;

    const int lr  = tid >> 2;        // A-load row 0..63
    const int lk4 = (tid & 3) * 4;   // A-load k offset {0,4,8,12}

    for (int k0 = 0; k0 < 128; k0 += 16) {
        // A tile (transposed into smem)
        {
            const int t  = t0 + lr;
            const int kg = k0 + lk4;
            float4 av = make_float4(0.f, 0.f, 0.f, 0.f);
            if (kg < 64) {
                const int ts = t - 1;
                if (ts >= 0)
                    av = *(const float4*)&x[((size_t)b * T_ + ts) * C_ + kg];
            } else {
                av = *(const float4*)&x[((size_t)b * T_ + t) * C_ + (kg - 64)];
            }
            As[lk4 + 0][lr] = av.x; As[lk4 + 1][lr] = av.y;
            As[lk4 + 2][lr] = av.z; As[lk4 + 3][lr] = av.w;
        }
        // B tile
        {
            const int kk = tid >> 4;
            const int nn = (tid & 15) * 4;
            *(float4*)&Bs[kk][nn] =
                *(const float4*)&Wc[(size_t)(k0 + kk) * F_ + n0 + nn];
        }
        __syncthreads();
        #pragma unroll
        for (int k = 0; k < 16; ++k) {
            float4 a4 = *(float4*)&As[k][ty * 4];
            float4 b4 = *(float4*)&Bs[k][tx * 4];
            float aa[4] = {a4.x, a4.y, a4.z, a4.w};
            float bb[4] = {b4.x, b4.y, b4.z, b4.w};
            #pragma unroll
            for (int i = 0; i < 4; ++i)
                #pragma unroll
                for (int j = 0; j < 4; ++j) acc[i][j] += aa[i] * bb[j];
        }
        __syncthreads();
    }
    #pragma unroll
    for (int i = 0; i < 4; ++i) {
        const int m = m0 + ty * 4 + i;
        *(float4*)&g_out[(size_t)m * F_ + n0 + tx * 4] =
            make_float4(acc[i][0], acc[i][1], acc[i][2], acc[i][3]);
    }
}

// ---------------------------------------------------------------------------
// gated: z = tanh(A@Wf) * sigmoid(A@Wg)
// A[m,k]: k<256 -> out[b,t-d,k] (0 if t<d), else out[b,t,k-256].
// Wf/Wg are contiguous [512,256]. Dual-B: f and g share A tile loads.
// ---------------------------------------------------------------------------
__global__ void gated_kernel(const float* __restrict__ Wf,
                             const float* __restrict__ Wg, int d) {
    __shared__ float As [16][64];
    __shared__ float Bfs[16][64];
    __shared__ float Bgs[16][64];
    const int tid = threadIdx.x;
    const int tx = tid & 15, ty = tid >> 4;
    const int m0 = blockIdx.x * 64;
    const int n0 = blockIdx.y * 64;
    const int b  = m0 / T_;
    const int t0 = m0 % T_;

    float accf[4][4], accg[4][4];
    #pragma unroll
    for (int i = 0; i < 4; ++i)
        #pragma unroll
        for (int j = 0; j < 4; ++j) { accf[i][j] = 0.0f; accg[i][j] = 0.0f; }

    const int lr  = tid >> 2;
    const int lk4 = (tid & 3) * 4;

    for (int k0 = 0; k0 < 512; k0 += 16) {
        {
            const int t  = t0 + lr;
            const int kg = k0 + lk4;
            float4 av = make_float4(0.f, 0.f, 0.f, 0.f);
            if (kg < 256) {
                const int ts = t - d;
                if (ts >= 0)
                    av = *(const float4*)&g_out[((size_t)b * T_ + ts) * F_ + kg];
            } else {
                av = *(const float4*)&g_out[((size_t)b * T_ + t) * F_ + (kg - 256)];
            }
            As[lk4 + 0][lr] = av.x; As[lk4 + 1][lr] = av.y;
            As[lk4 + 2][lr] = av.z; As[lk4 + 3][lr] = av.w;
        }
        {
            const int kk = tid >> 4;
            const int nn = (tid & 15) * 4;
            const size_t boff = (size_t)(k0 + kk) * F_ + n0 + nn;
            *(float4*)&Bfs[kk][nn] = *(const float4*)&Wf[boff];
            *(float4*)&Bgs[kk][nn] = *(const float4*)&Wg[boff];
        }
        __syncthreads();
        #pragma unroll
        for (int k = 0; k < 16; ++k) {
            float4 a4 = *(float4*)&As [k][ty * 4];
            float4 f4 = *(float4*)&Bfs[k][tx * 4];
            float4 g4 = *(float4*)&Bgs[k][tx * 4];
            float aa[4] = {a4.x, a4.y, a4.z, a4.w};
            float ff[4] = {f4.x, f4.y, f4.z, f4.w};
            float gg[4] = {g4.x, g4.y, g4.z, g4.w};
            #pragma unroll
            for (int i = 0; i < 4; ++i)
                #pragma unroll
                for (int j = 0; j < 4; ++j) {
                    accf[i][j] += aa[i] * ff[j];
                    accg[i][j] += aa[i] * gg[j];
                }
        }
        __syncthreads();
    }
    #pragma unroll
    for (int i = 0; i < 4; ++i) {
        const int m = m0 + ty * 4 + i;
        float4 zv;
        zv.x = tanhf(accf[i][0]) * sigmoidf_(accg[i][0]);
        zv.y = tanhf(accf[i][1]) * sigmoidf_(accg[i][1]);
        zv.z = tanhf(accf[i][2]) * sigmoidf_(accg[i][2]);
        zv.w = tanhf(accf[i][3]) * sigmoidf_(accg[i][3]);
        *(float4*)&g_z[(size_t)m * F_ + n0 + tx * 4] = zv;
    }
}

// ---------------------------------------------------------------------------
// res_skip: out += z@Wr + br ; skip (= or +=) z@Ws + bs
// ---------------------------------------------------------------------------
__global__ void res_skip_kernel(const float* __restrict__ Wr,
                                const float* __restrict__ br,
                                const float* __restrict__ Ws,
                                const float* __restrict__ bs,
                                int first) {
    __shared__ float As [16][64];
    __shared__ float Brs[16][64];
    __shared__ float Bss[16][64];
    const int tid = threadIdx.x;
    const int tx = tid & 15, ty = tid >> 4;
    const int m0 = blockIdx.x * 64;
    const int n0 = blockIdx.y * 64;

    float accr[4][4], accs[4][4];
    #pragma unroll
    for (int i = 0; i < 4; ++i)
        #pragma unroll
        for (int j = 0; j < 4; ++j) { accr[i][j] = 0.0f; accs[i][j] = 0.0f; }

    const int lr  = tid >> 2;
    const int lk4 = (tid & 3) * 4;

    for (int k0 = 0; k0 < 256; k0 += 16) {
        {
            const int m  = m0 + lr;
            const int kg = k0 + lk4;
            float4 av = *(const float4*)&g_z[(size_t)m * F_ + kg];
            As[lk4 + 0][lr] = av.x; As[lk4 + 1][lr] = av.y;
            As[lk4 + 2][lr] = av.z; As[lk4 + 3][lr] = av.w;
        }
        {
            const int kk = tid >> 4;
            const int nn = (tid & 15) * 4;
            const size_t boff = (size_t)(k0 + kk) * F_ + n0 + nn;
            *(float4*)&Brs[kk][nn] = *(const float4*)&Wr[boff];
            *(float4*)&Bss[kk][nn] = *(const float4*)&Ws[boff];
        }
        __syncthreads();
        #pragma unroll
        for (int k = 0; k < 16; ++k) {
            float4 a4 = *(float4*)&As [k][ty * 4];
            float4 r4 = *(float4*)&Brs[k][tx * 4];
            float4 s4 = *(float4*)&Bss[k][tx * 4];
            float aa[4] = {a4.x, a4.y, a4.z, a4.w};
            float rr[4] = {r4.x, r4.y, r4.z, r4.w};
            float ss[4] = {s4.x, s4.y, s4.z, s4.w};
            #pragma unroll
            for (int i = 0; i < 4; ++i)
                #pragma unroll
                for (int j = 0; j < 4; ++j) {
                    accr[i][j] += aa[i] * rr[j];
                    accs[i][j] += aa[i] * ss[j];
                }
        }
        __syncthreads();
    }
    const float4 br4 = *(const float4*)&br[n0 + tx * 4];
    const float4 bs4 = *(const float4*)&bs[n0 + tx * 4];
    #pragma unroll
    for (int i = 0; i < 4; ++i) {
        const int m = m0 + ty * 4 + i;
        const size_t off = (size_t)m * F_ + n0 + tx * 4;
        float4 o = *(float4*)&g_out[off];
        o.x += accr[i][0] + br4.x; o.y += accr[i][1] + br4.y;
        o.z += accr[i][2] + br4.z; o.w += accr[i][3] + br4.w;
        *(float4*)&g_out[off] = o;

        float4 s;
        if (first) {
            s = make_float4(0.f, 0.f, 0.f, 0.f);
        } else {
            s = *(float4*)&g_skip[off];
        }
        s.x += accs[i][0] + bs4.x; s.y += accs[i][1] + bs4.y;
        s.z += accs[i][2] + bs4.z; s.w += accs[i][3] + bs4.w;
        *(float4*)&g_skip[off] = s;
    }
}

// ---------------------------------------------------------------------------
// head: y = selu(selu(skip)@Wd1 + bd1)@Wd2 + bd2
// 256 threads = 4 rows x 64 lanes per block.
// ---------------------------------------------------------------------------
__global__ void head_kernel(const float* __restrict__ Wd1,
                            const float* __restrict__ bd1,
                            const float* __restrict__ Wd2,
                            const float* __restrict__ bd2,
                            float* __restrict__ y) {
    __shared__ float hs [4][256];
    __shared__ float h2s[4][64];
    const int row  = threadIdx.x >> 6;   // 0..3
    const int lane = threadIdx.x & 63;   // 0..63
    const int m = blockIdx.x * 4 + row;

    for (int j = lane; j < 256; j += 64)
        hs[row][j] = seluf_(g_skip[(size_t)m * F_ + j]);
    __syncthreads();

    float acc = bd1[lane];
    #pragma unroll 8
    for (int k = 0; k < 256; ++k)
        acc += hs[row][k] * __ldg(&Wd1[(size_t)k * C_ + lane]);
    h2s[row][lane] = seluf_(acc);
    __syncthreads();

    float acc2 = bd2[lane];
    #pragma unroll 8
    for (int k = 0; k < 64; ++k)
        acc2 += h2s[row][k] * __ldg(&Wd2[(size_t)k * C_ + lane]);
    y[(size_t)m * C_ + lane] = acc2;
}

// ---------------------------------------------------------------------------
extern "C" void kernel_launch(void* const* d_in, const int* in_sizes, int n_in,
                              void* d_out, int out_size) {
    const float* x   = (const float*)d_in[0];
    const float* Wc  = (const float*)d_in[1];
    const float* Wf  = (const float*)d_in[2];
    const float* Wg  = (const float*)d_in[3];
    const float* Wr  = (const float*)d_in[4];
    const float* br  = (const float*)d_in[5];
    const float* Ws  = (const float*)d_in[6];
    const float* bs  = (const float*)d_in[7];
    const float* Wd1 = (const float*)d_in[8];
    const float* bd1 = (const float*)d_in[9];
    const float* Wd2 = (const float*)d_in[10];
    const float* bd2 = (const float*)d_in[11];
    float* y = (float*)d_out;

    dim3 blk(256);
    dim3 grid_g(M_ / 64, F_ / 64);  // 512 x 4

    conv0_kernel<<<grid_g, blk>>>(x, Wc);
    for (int i = 0; i < NL; ++i) {
        const int d = 2 << i;  // 2^(i+1): 2,4,...,256
        gated_kernel<<<grid_g, blk>>>(Wf + (size_t)i * 2 * F_ * F_,
                                      Wg + (size_t)i * 2 * F_ * F_, d);
        res_skip_kernel<<<grid_g, blk>>>(Wr + (size_t)i * F_ * F_,
                                         br + (size_t)i * F_,
                                         Ws + (size_t)i * F_ * F_,
                                         bs + (size_t)i * F_, i == 0);
    }
    head_kernel<<<M_ / 4, blk>>>(Wd1, bd1, Wd2, bd2, y);
}